// round 3
// baseline (speedup 1.0000x reference)
#include <cuda_runtime.h>
#include <cstdint>

#define SEQ    2048
#define BATCH  512
#define INPT   64
#define HIDDEN 128
#define BB     2               // batch per recurrence block
#define NBLK   (BATCH / BB)    // 256 blocks -> 2 per SM
#define NTHR   256
#define KH     (HIDDEN / 2)    // 64 k per warp-half

// 512MB scratch: xp[t][b][j] = xs[t][b] @ W_ih^T + (b_ih + b_hh)
__device__ float g_xp[(size_t)SEQ * BATCH * HIDDEN];

// ---- packed f32x2 helpers (sm_103a) ----
__device__ __forceinline__ unsigned long long ffma2(unsigned long long a,
                                                    unsigned long long b,
                                                    unsigned long long c) {
    unsigned long long d;
    asm("fma.rn.f32x2 %0, %1, %2, %3;" : "=l"(d) : "l"(a), "l"(b), "l"(c));
    return d;
}
__device__ __forceinline__ float2 unpack2(unsigned long long v) {
    float2 r;
    asm("mov.b64 {%0, %1}, %2;" : "=f"(r.x), "=f"(r.y) : "l"(v));
    return r;
}
__device__ __forceinline__ float tanh_fast(float z) {
    float az = fabsf(z);
    float e  = __expf(-2.0f * az);
    float r  = __fdividef(1.0f - e, 1.0f + e);
    return copysignf(r, z);
}
__device__ __forceinline__ void cp16(void* smem_dst, const float* gsrc) {
    unsigned dst = (unsigned)__cvta_generic_to_shared(smem_dst);
    asm volatile("cp.async.ca.shared.global [%0], [%1], 16;" :: "r"(dst), "l"(gsrc));
}

// ============================================================================
// Kernel 1: time-parallel x-projection GEMM (register-resident W_ih, f32x2)
// ============================================================================
#define GTHR  256
#define GROWS 256                          // rows of X per block
#define GBLK  ((SEQ * BATCH) / GROWS)      // 4096 blocks

__global__ void __launch_bounds__(GTHR, 2)
xproj_kernel(const float* __restrict__ xs,
             const float* __restrict__ W_ih,
             const float* __restrict__ b_ih,
             const float* __restrict__ b_hh) {
    __shared__ __align__(16) unsigned long long xsh[2][4][INPT / 2]; // 4 rows x 64 f
    const int tid = threadIdx.x;
    const int j   = tid & (HIDDEN - 1);   // output column
    const int rh  = tid >> 7;             // row parity within 4-row group

    // Full K=64 weight row in registers as 32 f32x2 pairs (64 regs).
    unsigned long long w[INPT / 2];
    const unsigned long long* wr =
        reinterpret_cast<const unsigned long long*>(W_ih + (size_t)j * INPT);
    #pragma unroll
    for (int i = 0; i < INPT / 2; i++) w[i] = wr[i];
    const float bias = b_ih[j] + b_hh[j];

    const long row0 = (long)blockIdx.x * GROWS;

    // prime group 0: 4 rows x 64 floats = 1KB
    if (tid < 64) {
        int r = tid >> 4, seg = tid & 15;
        cp16(&xsh[0][r][seg * 2], xs + (row0 + r) * INPT + seg * 4);
    }
    asm volatile("cp.async.commit_group;" ::);

    for (int g = 0; g < GROWS / 4; ++g) {
        const int buf = g & 1;
        __syncthreads();   // readers of buf^1 (iter g-1) are done
        if (g + 1 < GROWS / 4 && tid < 64) {
            int r = tid >> 4, seg = tid & 15;
            cp16(&xsh[buf ^ 1][r][seg * 2],
                 xs + (row0 + (g + 1) * 4 + r) * INPT + seg * 4);
        }
        asm volatile("cp.async.commit_group;" ::);
        asm volatile("cp.async.wait_group 1;" ::);
        __syncthreads();

        #pragma unroll
        for (int rr = 0; rr < 2; ++rr) {
            const int r = rh + rr * 2;
            const ulonglong2* xr = reinterpret_cast<const ulonglong2*>(xsh[buf][r]);
            unsigned long long a0 = 0, a1 = 0, a2 = 0, a3 = 0;
            #pragma unroll
            for (int i = 0; i < 8; i++) {
                ulonglong2 q  = xr[2 * i];
                ulonglong2 q2 = xr[2 * i + 1];
                a0 = ffma2(w[4 * i],     q.x,  a0);
                a1 = ffma2(w[4 * i + 1], q.y,  a1);
                a2 = ffma2(w[4 * i + 2], q2.x, a2);
                a3 = ffma2(w[4 * i + 3], q2.y, a3);
            }
            float2 p0 = unpack2(a0), p1 = unpack2(a1);
            float2 p2 = unpack2(a2), p3 = unpack2(a3);
            float s = ((p0.x + p0.y) + (p1.x + p1.y))
                    + ((p2.x + p2.y) + (p3.x + p3.y));
            g_xp[(row0 + g * 4 + r) * HIDDEN + j] = s + bias;
        }
    }
}

// ============================================================================
// Kernel 2: serial recurrence, K=128, 2 blocks/SM, 1 barrier/step
// warp layout: j = wid*16 + (lane&15), half = lane>>4 (k [0,64) vs [64,128))
// ============================================================================
__global__ void __launch_bounds__(NTHR, 2)
rnn_kernel(const float* __restrict__ W_hh,
           const float* __restrict__ W_out,
           const float* __restrict__ b_out,
           float* __restrict__ out) {
    __shared__ __align__(16) float v[2][BB][HIDDEN];   // h double buffer
    __shared__ __align__(16) float xb[2][BB][HIDDEN];  // xp double buffer

    const int tid  = threadIdx.x;
    const int wid  = tid >> 5;
    const int lane = tid & 31;
    const int j    = wid * 16 + (lane & 15);
    const int k0   = (lane >> 4) * KH;          // 0 or 64
    const long bbase = (long)blockIdx.x * BB;

    // This thread's 64-k half of W_hh[j] as 32 f32x2 pairs (64 regs).
    unsigned long long w[KH / 2];
    const unsigned long long* wr =
        reinterpret_cast<const unsigned long long*>(W_hh + (size_t)j * HIDDEN + k0);
    #pragma unroll
    for (int i = 0; i < KH / 2; i++) w[i] = wr[i];

    // init: h0 = 0; stage xp(0)
    if (tid < HIDDEN) { v[0][0][tid] = 0.0f; v[0][1][tid] = 0.0f; }
    if (tid < 64) {
        int b = tid >> 5, seg = tid & 31;
        cp16(&xb[0][b][seg * 4], g_xp + (bbase + b) * HIDDEN + seg * 4);
    }
    asm volatile("cp.async.commit_group;" ::);
    asm volatile("cp.async.wait_group 0;" ::);
    __syncthreads();

    int cur = 0;
    for (int t = 0; t < SEQ; ++t) {
        const int nxt = cur ^ 1;

        // prefetch xp(t+1); xb[nxt] readers finished at last step's barrier
        if (t + 1 < SEQ && tid < 64) {
            int b = tid >> 5, seg = tid & 31;
            cp16(&xb[nxt][b][seg * 4],
                 g_xp + ((long)(t + 1) * BATCH + bbase + b) * HIDDEN + seg * 4);
        }
        asm volatile("cp.async.commit_group;" ::);

        float hn[BB];
        #pragma unroll
        for (int b = 0; b < BB; b++) {
            const ulonglong2* hp =
                reinterpret_cast<const ulonglong2*>(&v[cur][b][k0]);
            unsigned long long a0 = 0, a1 = 0, a2 = 0, a3 = 0;
            #pragma unroll
            for (int i = 0; i < 8; i++) {
                ulonglong2 q  = hp[2 * i];
                ulonglong2 q2 = hp[2 * i + 1];
                a0 = ffma2(w[4 * i],     q.x,  a0);
                a1 = ffma2(w[4 * i + 1], q.y,  a1);
                a2 = ffma2(w[4 * i + 2], q2.x, a2);
                a3 = ffma2(w[4 * i + 3], q2.y, a3);
            }
            float2 p0 = unpack2(a0), p1 = unpack2(a1);
            float2 p2 = unpack2(a2), p3 = unpack2(a3);
            float s = ((p0.x + p0.y) + (p1.x + p1.y))
                    + ((p2.x + p2.y) + (p3.x + p3.y));
            s += __shfl_xor_sync(0xffffffffu, s, 16);   // combine k-halves
            hn[b] = s + xb[cur][b][j];
        }
        if (lane < 16) {
            #pragma unroll
            for (int b = 0; b < BB; b++)
                v[nxt][b][j] = tanh_fast(hn[b]);
        }
        asm volatile("cp.async.wait_group 0;" ::);
        __syncthreads();
        cur = nxt;
    }

    // output projection: out[b] = h_final[b] . W_out + b_out  (cur == 0)
    if (tid < BB * 32) {
        int b = tid >> 5, l = tid & 31;
        float s = 0.0f;
        #pragma unroll
        for (int m = 0; m < 4; m++) {
            int jj = l + 32 * m;
            s += v[cur][b][jj] * W_out[jj];
        }
        #pragma unroll
        for (int off = 16; off; off >>= 1)
            s += __shfl_down_sync(0xffffffffu, s, off);
        if (l == 0) out[bbase + b] = s + b_out[0];
    }
}

extern "C" void kernel_launch(void* const* d_in, const int* in_sizes, int n_in,
                              void* d_out, int out_size) {
    const float* xs    = (const float*)d_in[0];
    const float* W_ih  = (const float*)d_in[1];
    const float* W_hh  = (const float*)d_in[2];
    const float* b_ih  = (const float*)d_in[3];
    const float* b_hh  = (const float*)d_in[4];
    const float* W_out = (const float*)d_in[5];
    const float* b_out = (const float*)d_in[6];

    xproj_kernel<<<GBLK, GTHR>>>(xs, W_ih, b_ih, b_hh);
    rnn_kernel<<<NBLK, NTHR>>>(W_hh, W_out, b_out, (float*)d_out);
}